// round 16
// baseline (speedup 1.0000x reference)
#include <cuda_runtime.h>
#include <math.h>

#define FHH 200
#define FWW 200
#define NPIX 40000
#define CIN 256
#define COUT 256
#define KD 2304
#define NANCH 120000
#define TOPK 1000
#define HBINS 16384
#define MAXCAND 4096
#define XCLIP 4.135166556742356f
#define KC_TILES 40   /* 320 k-elements per Eigen panel / 8 per tile */
#define NTILES (KD / 8)

// ---------------- scratch (static device globals; no allocation) ----------------
__device__ float d_wt[KD * COUT];           // transposed weights [k][m], k = rs*256+c
__device__ float d_tt[(size_t)NPIX * COUT]; // conv output (relu), PIXEL-MAJOR [p][c]
__device__ float d_scores[NANCH];
__device__ float d_deltas[NANCH * 4];
__device__ int   d_hist[HBINS];
__device__ int   d_cutbin;
__device__ int   d_cand_cnt;
__device__ float d_cand_val[MAXCAND];
__device__ int   d_cand_idx[MAXCAND];
__device__ float d_top_score[TOPK];
__device__ int   d_top_idx[TOPK];
__device__ float d_boxes[TOPK * 4];
__device__ unsigned d_validw[32];
__device__ unsigned d_mask[TOPK * 32];

// cell anchors: a=0:(-23,-11,23,11) a=1:(-16,-16,16,16) a=2:(-11,-23,11,23)
__constant__ float c_ax1[3] = {-23.f, -16.f, -11.f};
__constant__ float c_ay1[3] = {-11.f, -16.f, -23.f};
__constant__ float c_ax2[3] = { 23.f,  16.f,  11.f};
__constant__ float c_ay2[3] = { 11.f,  16.f,  23.f};

// ---------------- weight transpose (32x32 smem-tiled, coalesced both sides) ----------------
// W viewed as [256 m][2304 kk], kk = c*9 + rs; d_wt[k][m] with k = rs*256 + c.
// Grid (72, 8), block (32, 8): each block transposes a 32(kk) x 32(m) tile.
__global__ void wtrans_kernel(const float* __restrict__ W) {
    __shared__ float tile[32][33];
    int tx = threadIdx.x, ty = threadIdx.y;

    // merged counter zeroing
    {
        int bid = blockIdx.y * 72 + blockIdx.x;
        int gid = bid * 256 + ty * 32 + tx;
        if (gid < HBINS) d_hist[gid] = 0;
        if (gid == 0) d_cand_cnt = 0;
    }

    int kk0 = blockIdx.x * 32;
    int m0 = blockIdx.y * 32;

#pragma unroll
    for (int j = 0; j < 4; j++) {
        int m = m0 + ty * 4 + j;
        tile[ty * 4 + j][tx] = W[(size_t)m * KD + kk0 + tx];   // coalesced along kk
    }
    __syncthreads();
#pragma unroll
    for (int j = 0; j < 4; j++) {
        int kk = kk0 + ty * 4 + j;
        int c = kk / 9;
        int rs = kk - c * 9;
        int k = rs * 256 + c;
        d_wt[(size_t)k * COUT + m0 + tx] = tile[tx][ty * 4 + j];  // coalesced along m
    }
}

// ---------------- 3x3 conv + bias + relu as implicit GEMM (R12 — frozen) ----------------
// Eigen-threaded-gebp replication (bit-identical chain since R8):
//   k = (r*3+s)*256 + c (c fastest), sequential FMA within 320-wide k panels,
//   panel sums combined left-associatively.
__global__ void __launch_bounds__(256)
conv3x3_relu(const float* __restrict__ feat, const float* __restrict__ bias) {
    __shared__ float sW[2][8][128];
    __shared__ float sX[2][8][128];

    const int n0 = blockIdx.x * 128;   // pixel tile
    const int m0 = blockIdx.y * 128;   // out-channel tile
    const int tid = threadIdx.x;
    const int tx = tid & 15;           // pixel micro
    const int ty = tid >> 4;           // channel micro
    const int kx = tid >> 5;           // load row (0..7)
    const int lane = tid & 31;

    int py[4], pxc[4];
    bool pin[4];
#pragma unroll
    for (int q = 0; q < 4; q++) {
        int p = n0 + lane + q * 32;
        pin[q] = p < NPIX;
        int y = p / 200;
        py[q] = y;
        pxc[q] = p - 200 * y;
    }

    float tot[8][8];   // completed panel sums
    float pac[8][8];   // current panel accumulator
#pragma unroll
    for (int i = 0; i < 8; i++)
#pragma unroll
        for (int j = 0; j < 8; j++) { tot[i][j] = 0.f; pac[i][j] = 0.f; }

    float4 wv;
    float  xv0, xv1, xv2, xv3;

#define CONV_LOAD(T) do {                                                     \
        int k0n = (T) * 8;                                                    \
        int rsn = k0n >> 8, c0n = k0n & 255;                                  \
        wv = *(const float4*)(d_wt + (size_t)(k0n + kx) * COUT + m0 + lane * 4); \
        int rr = rsn / 3, ss = rsn - 3 * rr;                                  \
        const float* fb = feat + (size_t)(c0n + kx) * NPIX;                   \
        int yy0 = py[0] + rr - 1, xx0 = pxc[0] + ss - 1;                      \
        int yy1 = py[1] + rr - 1, xx1 = pxc[1] + ss - 1;                      \
        int yy2 = py[2] + rr - 1, xx2 = pxc[2] + ss - 1;                      \
        int yy3 = py[3] + rr - 1, xx3 = pxc[3] + ss - 1;                      \
        xv0 = (pin[0] && (unsigned)yy0 < 200u && (unsigned)xx0 < 200u) ? fb[yy0 * 200 + xx0] : 0.f; \
        xv1 = (pin[1] && (unsigned)yy1 < 200u && (unsigned)xx1 < 200u) ? fb[yy1 * 200 + xx1] : 0.f; \
        xv2 = (pin[2] && (unsigned)yy2 < 200u && (unsigned)xx2 < 200u) ? fb[yy2 * 200 + xx2] : 0.f; \
        xv3 = (pin[3] && (unsigned)yy3 < 200u && (unsigned)xx3 < 200u) ? fb[yy3 * 200 + xx3] : 0.f; \
    } while (0)

#define CONV_STORE(BUF) do {                                                  \
        *(float4*)&sW[BUF][kx][lane * 4] = wv;                                \
        sX[BUF][kx][lane]      = xv0;                                         \
        sX[BUF][kx][lane + 32] = xv1;                                         \
        sX[BUF][kx][lane + 64] = xv2;                                         \
        sX[BUF][kx][lane + 96] = xv3;                                         \
    } while (0)

#define CONV_FOLD() do {                                                      \
        _Pragma("unroll")                                                     \
        for (int i = 0; i < 8; i++)                                           \
            _Pragma("unroll")                                                 \
            for (int j = 0; j < 8; j++) { tot[i][j] += pac[i][j]; pac[i][j] = 0.f; } \
    } while (0)

#define CONV_COMPUTE(BUF) do {                                                \
        _Pragma("unroll")                                                     \
        for (int k = 0; k < 8; k++) {                                         \
            float a[8], b[8];                                                 \
            *(float4*)(a)     = *(const float4*)&sW[BUF][k][ty * 8];          \
            *(float4*)(a + 4) = *(const float4*)&sW[BUF][k][ty * 8 + 4];      \
            *(float4*)(b)     = *(const float4*)&sX[BUF][k][tx * 8];          \
            *(float4*)(b + 4) = *(const float4*)&sX[BUF][k][tx * 8 + 4];      \
            _Pragma("unroll")                                                 \
            for (int i = 0; i < 8; i++)                                       \
                _Pragma("unroll")                                             \
                for (int j = 0; j < 8; j++) pac[i][j] = fmaf(a[i], b[j], pac[i][j]); \
        }                                                                     \
    } while (0)

    // prologue: tile 0 -> buf 0
    CONV_LOAD(0);
    CONV_STORE(0);
    __syncthreads();

    for (int t = 0; t < NTILES; t += 2) {
        // even iter: tile t in buf 0
        if (t + 1 < NTILES) CONV_LOAD(t + 1);
        if (t > 0 && (t % KC_TILES) == 0) CONV_FOLD();
        CONV_COMPUTE(0);
        if (t + 1 < NTILES) CONV_STORE(1);
        __syncthreads();
        // odd iter: tile t+1 in buf 1
        if (t + 2 < NTILES) CONV_LOAD(t + 2);
        if (((t + 1) % KC_TILES) == 0) CONV_FOLD();
        CONV_COMPUTE(1);
        if (t + 2 < NTILES) CONV_STORE(0);
        __syncthreads();
    }
    // final (short) panel
    CONV_FOLD();

    // epilogue: pixel-major writes, 2x float4 (8 contiguous channels) per pixel
    {
        float bv[8];
#pragma unroll
        for (int i = 0; i < 8; i++) bv[i] = bias[m0 + ty * 8 + i];
#pragma unroll
        for (int j = 0; j < 8; j++) {
            int p = n0 + tx * 8 + j;
            if (p < NPIX) {
                float* dst = d_tt + (size_t)p * COUT + m0 + ty * 8;
                float4 v0, v1;
                v0.x = fmaxf(tot[0][j] + bv[0], 0.f);
                v0.y = fmaxf(tot[1][j] + bv[1], 0.f);
                v0.z = fmaxf(tot[2][j] + bv[2], 0.f);
                v0.w = fmaxf(tot[3][j] + bv[3], 0.f);
                v1.x = fmaxf(tot[4][j] + bv[4], 0.f);
                v1.y = fmaxf(tot[5][j] + bv[5], 0.f);
                v1.z = fmaxf(tot[6][j] + bv[6], 0.f);
                v1.w = fmaxf(tot[7][j] + bv[7], 0.f);
                *(float4*)dst = v0;
                *(float4*)(dst + 4) = v1;
            }
        }
    }
#undef CONV_LOAD
#undef CONV_STORE
#undef CONV_FOLD
#undef CONV_COMPUTE
}

// ---------------- 1x1 heads (R12 tail — proven) ----------------
// K=256 < 320 -> single Eigen panel: ONE strict sequential FMA chain over c.
__global__ void __launch_bounds__(128)
head_kernel(const float* __restrict__ cls_w, const float* __restrict__ cls_b,
            const float* __restrict__ bbox_w, const float* __restrict__ bbox_b) {
    __shared__ float sw[15][256];
    int tid = threadIdx.x;
    for (int i = tid; i < 15 * 256; i += 128) {
        int o = i >> 8, c = i & 255;
        sw[o][c] = (o < 3) ? cls_w[o * 256 + c] : bbox_w[(o - 3) * 256 + c];
    }
    __syncthreads();

    int p = blockIdx.x * 128 + tid;
    if (p >= NPIX) return;

    const float4* row = (const float4*)(d_tt + (size_t)p * COUT);

    float acc[15];
#pragma unroll
    for (int o = 0; o < 15; o++) acc[o] = 0.f;

#pragma unroll 8
    for (int cc = 0; cc < 64; cc++) {
        float4 v = row[cc];
#pragma unroll
        for (int o = 0; o < 15; o++) {
            float4 w4 = *(const float4*)&sw[o][cc * 4];
            acc[o] = fmaf(w4.x, v.x, acc[o]);
            acc[o] = fmaf(w4.y, v.y, acc[o]);
            acc[o] = fmaf(w4.z, v.z, acc[o]);
            acc[o] = fmaf(w4.w, v.w, acc[o]);
        }
    }

#pragma unroll
    for (int a = 0; a < 3; a++) {
        float sc = acc[a] + cls_b[a];
        d_scores[p * 3 + a] = sc;
        unsigned kb = __float_as_uint(sc);
        kb = (kb & 0x80000000u) ? ~kb : (kb | 0x80000000u);
        atomicAdd(&d_hist[kb >> 18], 1);
#pragma unroll
        for (int j = 0; j < 4; j++)
            d_deltas[(p * 3 + a) * 4 + j] = acc[3 + a * 4 + j] + bbox_b[a * 4 + j];
    }
}

// ---------------- top-k: find cutoff histogram bin (vectorized) ----------------
__global__ void scan_kernel() {
    __shared__ int psum[256];
    int tid = threadIdx.x;
    const int4* h4 = (const int4*)&d_hist[tid * 64];
    int s = 0;
#pragma unroll
    for (int i = 0; i < 16; i++) {
        int4 v = h4[i];
        s += v.x + v.y + v.z + v.w;
    }
    psum[tid] = s;
    __syncthreads();
    if (tid == 0) {
        int acc = 0;
        int b = 0;
        for (b = 255; b >= 0; b--) {
            if (acc + psum[b] >= TOPK) break;
            acc += psum[b];
        }
        int bin = b * 64;
        for (int i = 63; i >= 0; i--) {
            int c = d_hist[b * 64 + i];
            if (acc + c >= TOPK) { bin = b * 64 + i; break; }
            acc += c;
        }
        d_cutbin = bin;
    }
}

// ---------------- collect candidates with bin >= cutoff ----------------
__global__ void collect_kernel() {
    int i = blockIdx.x * 256 + threadIdx.x;
    if (i >= NANCH) return;
    float v = d_scores[i];
    unsigned kb = __float_as_uint(v);
    kb = (kb & 0x80000000u) ? ~kb : (kb | 0x80000000u);
    if ((int)(kb >> 18) >= d_cutbin) {
        int pos = atomicAdd(&d_cand_cnt, 1);
        if (pos < MAXCAND) { d_cand_val[pos] = v; d_cand_idx[pos] = i; }
    }
}

// ---------------- bitonic sort candidates (desc by value, asc by idx) ----------------
// Dynamic network size: 2048 when cand_cnt fits (typical ~1200), else 4096.
__global__ void __launch_bounds__(1024) sort_kernel() {
    __shared__ float sv[MAXCAND];
    __shared__ int   si[MAXCAND];
    int tid = threadIdx.x;
    int n = d_cand_cnt;
    if (n > MAXCAND) n = MAXCAND;
    const int S = (n <= 2048) ? 2048 : 4096;
    for (int i = tid; i < S; i += 1024) {
        if (i < n) { sv[i] = d_cand_val[i]; si[i] = d_cand_idx[i]; }
        else       { sv[i] = -INFINITY;     si[i] = 0x7fffffff;   }
    }
    __syncthreads();
    for (int size = 2; size <= S; size <<= 1) {
        for (int stride = size >> 1; stride > 0; stride >>= 1) {
            for (int t = tid; t < S / 2; t += 1024) {
                int i = 2 * t - (t & (stride - 1));
                int j = i + stride;
                bool desc = ((i & size) == 0);
                float av = sv[i], bv = sv[j];
                int ai = si[i], bi = si[j];
                bool a_first = (av > bv) || (av == bv && ai < bi);
                if (desc != a_first) { sv[i] = bv; sv[j] = av; si[i] = bi; si[j] = ai; }
            }
            __syncthreads();
        }
    }
    for (int i = tid; i < TOPK; i += 1024) {
        d_top_score[i] = sv[i];
        d_top_idx[i] = si[i];
    }
}

// ---------------- decode + clip + valid ----------------
__global__ void __launch_bounds__(1024) decode_kernel(const int* pih, const int* piw) {
    int i = threadIdx.x;
    int vbit = 0;
    if (i < TOPK) {
        int idx = d_top_idx[i];
        int p = idx / 3;
        int a = idx - 3 * p;
        int y = p / 200;
        int x = p - 200 * y;
        int ih = pih[0], iw = piw[0];
        float sh = (float)(ih / FHH), swd = (float)(iw / FWW);
        float a1 = x * swd + c_ax1[a];
        float b1 = y * sh  + c_ay1[a];
        float a2 = x * swd + c_ax2[a];
        float b2 = y * sh  + c_ay2[a];
        float w = a2 - a1, h = b2 - b1;
        float cx = a1 + 0.5f * w, cy = b1 + 0.5f * h;
        float dx = d_deltas[idx * 4 + 0];
        float dy = d_deltas[idx * 4 + 1];
        float dw = fminf(d_deltas[idx * 4 + 2], XCLIP);
        float dh = fminf(d_deltas[idx * 4 + 3], XCLIP);
        float pcx = dx * w + cx, pcy = dy * h + cy;
        // correctly-rounded float exp via double (matches libm expf on host)
        float pw = (float)exp((double)dw) * w, ph = (float)exp((double)dh) * h;
        float x1 = pcx - 0.5f * pw, y1 = pcy - 0.5f * ph;
        float x2 = pcx + 0.5f * pw, y2 = pcy + 0.5f * ph;
        float fw_ = (float)iw, fh_ = (float)ih;
        x1 = fminf(fmaxf(x1, 0.f), fw_);
        y1 = fminf(fmaxf(y1, 0.f), fh_);
        x2 = fminf(fmaxf(x2, 0.f), fw_);
        y2 = fminf(fmaxf(y2, 0.f), fh_);
        d_boxes[i * 4 + 0] = x1;
        d_boxes[i * 4 + 1] = y1;
        d_boxes[i * 4 + 2] = x2;
        d_boxes[i * 4 + 3] = y2;
        vbit = (x2 - x1 >= 0.001f) && (y2 - y1 >= 0.001f);
    }
    unsigned bal = __ballot_sync(0xffffffffu, vbit);
    if ((threadIdx.x & 31) == 0) d_validw[threadIdx.x >> 5] = bal;
}

// ---------------- IoU suppression bitmask ----------------
__global__ void mask_kernel() {
    int i = blockIdx.x;
    int w = threadIdx.x;
    float ix1 = d_boxes[i * 4 + 0], iy1 = d_boxes[i * 4 + 1];
    float ix2 = d_boxes[i * 4 + 2], iy2 = d_boxes[i * 4 + 3];
    float ia = (ix2 - ix1) * (iy2 - iy1);
    unsigned m = 0;
    int jbase = w * 32;
    for (int b = 0; b < 32; b++) {
        int j = jbase + b;
        if (j > i && j < TOPK) {
            float jx1 = d_boxes[j * 4 + 0], jy1 = d_boxes[j * 4 + 1];
            float jx2 = d_boxes[j * 4 + 2], jy2 = d_boxes[j * 4 + 3];
            float ja = (jx2 - jx1) * (jy2 - jy1);
            float xl = fmaxf(ix1, jx1), yt = fmaxf(iy1, jy1);
            float xr = fminf(ix2, jx2), yb = fminf(iy2, jy2);
            float inter = fmaxf(xr - xl, 0.f) * fmaxf(yb - yt, 0.f);
            float uni = ia + ja - inter;
            float iou = inter / (uni + 1e-8f);
            if (iou > 0.7f) m |= 1u << b;
        }
    }
    d_mask[i * 32 + w] = m;
}

// ---------------- serial greedy NMS (warp 0) + output write ----------------
__global__ void __launch_bounds__(1024) nms_out_kernel(float* out, int out_size) {
    __shared__ unsigned skeep[32];
    int tid = threadIdx.x;
    if (tid < 32) {
        unsigned myk = d_validw[tid];
        unsigned nextm = d_mask[tid];   // row 0
        for (int i = 0; i < TOPK; i++) {
            unsigned m = nextm;
            if (i + 1 < TOPK) nextm = d_mask[(i + 1) * 32 + tid];
            unsigned wv = __shfl_sync(0xffffffffu, myk, i >> 5);
            if ((wv >> (i & 31)) & 1u) myk &= ~m;
        }
        skeep[tid] = myk;
    }
    __syncthreads();
    for (int i = tid; i < TOPK; i += 1024) {
        bool k = (skeep[i >> 5] >> (i & 31)) & 1u;
        float x1 = 0.f, y1 = 0.f, x2 = 0.f, y2 = 0.f, sc = 0.f;
        if (k) {
            x1 = d_boxes[i * 4 + 0];
            y1 = d_boxes[i * 4 + 1];
            x2 = d_boxes[i * 4 + 2];
            y2 = d_boxes[i * 4 + 3];
            sc = d_top_score[i];
        }
        out[i * 5 + 0] = x1;
        out[i * 5 + 1] = y1;
        out[i * 5 + 2] = x2;
        out[i * 5 + 3] = y2;
        out[i * 5 + 4] = sc;
        if (out_size >= TOPK * 6) out[TOPK * 5 + i] = k ? 1.f : 0.f;
    }
}

// ---------------- launch ----------------
extern "C" void kernel_launch(void* const* d_in, const int* in_sizes, int n_in,
                              void* d_out, int out_size) {
    const float* feat   = (const float*)d_in[0];
    const float* conv_w = (const float*)d_in[1];
    const float* conv_b = (const float*)d_in[2];
    const float* cls_w  = (const float*)d_in[3];
    const float* cls_b  = (const float*)d_in[4];
    const float* bbox_w = (const float*)d_in[5];
    const float* bbox_b = (const float*)d_in[6];
    const int*   ih     = (const int*)d_in[7];
    const int*   iw     = (const int*)d_in[8];
    (void)in_sizes; (void)n_in;

    dim3 tgrid(KD / 32, COUT / 32);
    dim3 tblk(32, 8);
    wtrans_kernel<<<tgrid, tblk>>>(conv_w);
    dim3 cgrid((NPIX + 127) / 128, COUT / 128);
    conv3x3_relu<<<cgrid, 256>>>(feat, conv_b);
    head_kernel<<<(NPIX + 127) / 128, 128>>>(cls_w, cls_b, bbox_w, bbox_b);
    scan_kernel<<<1, 256>>>();
    collect_kernel<<<(NANCH + 255) / 256, 256>>>();
    sort_kernel<<<1, 1024>>>();
    decode_kernel<<<1, 1024>>>(ih, iw);
    mask_kernel<<<TOPK, 32>>>();
    nms_out_kernel<<<1, 1024>>>((float*)d_out, out_size);
}

// round 17
// speedup vs baseline: 1.0433x; 1.0433x over previous
#include <cuda_runtime.h>
#include <math.h>

#define FHH 200
#define FWW 200
#define NPIX 40000
#define CIN 256
#define COUT 256
#define KD 2304
#define NANCH 120000
#define TOPK 1000
#define HBINS 16384
#define MAXCAND 4096
#define XCLIP 4.135166556742356f
#define KC_TILES 40   /* 320 k-elements per Eigen panel / 8 per tile */
#define NTILES (KD / 8)

// ---------------- scratch (static device globals; no allocation) ----------------
__device__ float d_wt[KD * COUT];           // transposed weights [k][m], k = rs*256+c
__device__ float d_tt[(size_t)NPIX * COUT]; // conv output (relu), PIXEL-MAJOR [p][c]
__device__ float d_scores[NANCH];
__device__ float d_deltas[NANCH * 4];
__device__ int   d_hist[HBINS];
__device__ int   d_cutbin;
__device__ int   d_cand_cnt;
__device__ float d_cand_val[MAXCAND];
__device__ int   d_cand_idx[MAXCAND];
__device__ float d_top_score[TOPK];
__device__ int   d_top_idx[TOPK];
__device__ float d_boxes[TOPK * 4];
__device__ unsigned d_validw[32];
__device__ unsigned d_mask[TOPK * 32];

// cell anchors: a=0:(-23,-11,23,11) a=1:(-16,-16,16,16) a=2:(-11,-23,11,23)
__constant__ float c_ax1[3] = {-23.f, -16.f, -11.f};
__constant__ float c_ay1[3] = {-11.f, -16.f, -23.f};
__constant__ float c_ax2[3] = { 23.f,  16.f,  11.f};
__constant__ float c_ay2[3] = { 11.f,  16.f,  23.f};

// ---------------- weight transpose (32x32 smem-tiled, coalesced both sides) ----------------
// W viewed as [256 m][2304 kk], kk = c*9 + rs; d_wt[k][m] with k = rs*256 + c.
// Grid (72, 8), block (32, 8): each block transposes a 32(kk) x 32(m) tile.
__global__ void wtrans_kernel(const float* __restrict__ W) {
    __shared__ float tile[32][33];
    int tx = threadIdx.x, ty = threadIdx.y;

    // merged counter zeroing
    {
        int bid = blockIdx.y * 72 + blockIdx.x;
        int gid = bid * 256 + ty * 32 + tx;
        if (gid < HBINS) d_hist[gid] = 0;
        if (gid == 0) d_cand_cnt = 0;
    }

    int kk0 = blockIdx.x * 32;
    int m0 = blockIdx.y * 32;

#pragma unroll
    for (int j = 0; j < 4; j++) {
        int m = m0 + ty * 4 + j;
        tile[ty * 4 + j][tx] = W[(size_t)m * KD + kk0 + tx];   // coalesced along kk
    }
    __syncthreads();
#pragma unroll
    for (int j = 0; j < 4; j++) {
        int kk = kk0 + ty * 4 + j;
        int c = kk / 9;
        int rs = kk - c * 9;
        int k = rs * 256 + c;
        d_wt[(size_t)k * COUT + m0 + tx] = tile[tx][ty * 4 + j];  // coalesced along m
    }
}

// ---------------- 3x3 conv + bias + relu as implicit GEMM (R12 — frozen) ----------------
// Eigen-threaded-gebp replication (bit-identical chain since R8):
//   k = (r*3+s)*256 + c (c fastest), sequential FMA within 320-wide k panels,
//   panel sums combined left-associatively.
__global__ void __launch_bounds__(256)
conv3x3_relu(const float* __restrict__ feat, const float* __restrict__ bias) {
    __shared__ float sW[2][8][128];
    __shared__ float sX[2][8][128];

    const int n0 = blockIdx.x * 128;   // pixel tile
    const int m0 = blockIdx.y * 128;   // out-channel tile
    const int tid = threadIdx.x;
    const int tx = tid & 15;           // pixel micro
    const int ty = tid >> 4;           // channel micro
    const int kx = tid >> 5;           // load row (0..7)
    const int lane = tid & 31;

    int py[4], pxc[4];
    bool pin[4];
#pragma unroll
    for (int q = 0; q < 4; q++) {
        int p = n0 + lane + q * 32;
        pin[q] = p < NPIX;
        int y = p / 200;
        py[q] = y;
        pxc[q] = p - 200 * y;
    }

    float tot[8][8];   // completed panel sums
    float pac[8][8];   // current panel accumulator
#pragma unroll
    for (int i = 0; i < 8; i++)
#pragma unroll
        for (int j = 0; j < 8; j++) { tot[i][j] = 0.f; pac[i][j] = 0.f; }

    float4 wv;
    float  xv0, xv1, xv2, xv3;

#define CONV_LOAD(T) do {                                                     \
        int k0n = (T) * 8;                                                    \
        int rsn = k0n >> 8, c0n = k0n & 255;                                  \
        wv = *(const float4*)(d_wt + (size_t)(k0n + kx) * COUT + m0 + lane * 4); \
        int rr = rsn / 3, ss = rsn - 3 * rr;                                  \
        const float* fb = feat + (size_t)(c0n + kx) * NPIX;                   \
        int yy0 = py[0] + rr - 1, xx0 = pxc[0] + ss - 1;                      \
        int yy1 = py[1] + rr - 1, xx1 = pxc[1] + ss - 1;                      \
        int yy2 = py[2] + rr - 1, xx2 = pxc[2] + ss - 1;                      \
        int yy3 = py[3] + rr - 1, xx3 = pxc[3] + ss - 1;                      \
        xv0 = (pin[0] && (unsigned)yy0 < 200u && (unsigned)xx0 < 200u) ? fb[yy0 * 200 + xx0] : 0.f; \
        xv1 = (pin[1] && (unsigned)yy1 < 200u && (unsigned)xx1 < 200u) ? fb[yy1 * 200 + xx1] : 0.f; \
        xv2 = (pin[2] && (unsigned)yy2 < 200u && (unsigned)xx2 < 200u) ? fb[yy2 * 200 + xx2] : 0.f; \
        xv3 = (pin[3] && (unsigned)yy3 < 200u && (unsigned)xx3 < 200u) ? fb[yy3 * 200 + xx3] : 0.f; \
    } while (0)

#define CONV_STORE(BUF) do {                                                  \
        *(float4*)&sW[BUF][kx][lane * 4] = wv;                                \
        sX[BUF][kx][lane]      = xv0;                                         \
        sX[BUF][kx][lane + 32] = xv1;                                         \
        sX[BUF][kx][lane + 64] = xv2;                                         \
        sX[BUF][kx][lane + 96] = xv3;                                         \
    } while (0)

#define CONV_FOLD() do {                                                      \
        _Pragma("unroll")                                                     \
        for (int i = 0; i < 8; i++)                                           \
            _Pragma("unroll")                                                 \
            for (int j = 0; j < 8; j++) { tot[i][j] += pac[i][j]; pac[i][j] = 0.f; } \
    } while (0)

#define CONV_COMPUTE(BUF) do {                                                \
        _Pragma("unroll")                                                     \
        for (int k = 0; k < 8; k++) {                                         \
            float a[8], b[8];                                                 \
            *(float4*)(a)     = *(const float4*)&sW[BUF][k][ty * 8];          \
            *(float4*)(a + 4) = *(const float4*)&sW[BUF][k][ty * 8 + 4];      \
            *(float4*)(b)     = *(const float4*)&sX[BUF][k][tx * 8];          \
            *(float4*)(b + 4) = *(const float4*)&sX[BUF][k][tx * 8 + 4];      \
            _Pragma("unroll")                                                 \
            for (int i = 0; i < 8; i++)                                       \
                _Pragma("unroll")                                             \
                for (int j = 0; j < 8; j++) pac[i][j] = fmaf(a[i], b[j], pac[i][j]); \
        }                                                                     \
    } while (0)

    // prologue: tile 0 -> buf 0
    CONV_LOAD(0);
    CONV_STORE(0);
    __syncthreads();

    for (int t = 0; t < NTILES; t += 2) {
        // even iter: tile t in buf 0
        if (t + 1 < NTILES) CONV_LOAD(t + 1);
        if (t > 0 && (t % KC_TILES) == 0) CONV_FOLD();
        CONV_COMPUTE(0);
        if (t + 1 < NTILES) CONV_STORE(1);
        __syncthreads();
        // odd iter: tile t+1 in buf 1
        if (t + 2 < NTILES) CONV_LOAD(t + 2);
        if (((t + 1) % KC_TILES) == 0) CONV_FOLD();
        CONV_COMPUTE(1);
        if (t + 2 < NTILES) CONV_STORE(0);
        __syncthreads();
    }
    // final (short) panel
    CONV_FOLD();

    // epilogue: pixel-major writes, 2x float4 (8 contiguous channels) per pixel
    {
        float bv[8];
#pragma unroll
        for (int i = 0; i < 8; i++) bv[i] = bias[m0 + ty * 8 + i];
#pragma unroll
        for (int j = 0; j < 8; j++) {
            int p = n0 + tx * 8 + j;
            if (p < NPIX) {
                float* dst = d_tt + (size_t)p * COUT + m0 + ty * 8;
                float4 v0, v1;
                v0.x = fmaxf(tot[0][j] + bv[0], 0.f);
                v0.y = fmaxf(tot[1][j] + bv[1], 0.f);
                v0.z = fmaxf(tot[2][j] + bv[2], 0.f);
                v0.w = fmaxf(tot[3][j] + bv[3], 0.f);
                v1.x = fmaxf(tot[4][j] + bv[4], 0.f);
                v1.y = fmaxf(tot[5][j] + bv[5], 0.f);
                v1.z = fmaxf(tot[6][j] + bv[6], 0.f);
                v1.w = fmaxf(tot[7][j] + bv[7], 0.f);
                *(float4*)dst = v0;
                *(float4*)(dst + 4) = v1;
            }
        }
    }
#undef CONV_LOAD
#undef CONV_STORE
#undef CONV_FOLD
#undef CONV_COMPUTE
}

// ---------------- 1x1 heads (R12 tail — proven) ----------------
// K=256 < 320 -> single Eigen panel: ONE strict sequential FMA chain over c.
__global__ void __launch_bounds__(128)
head_kernel(const float* __restrict__ cls_w, const float* __restrict__ cls_b,
            const float* __restrict__ bbox_w, const float* __restrict__ bbox_b) {
    __shared__ float sw[15][256];
    int tid = threadIdx.x;
    for (int i = tid; i < 15 * 256; i += 128) {
        int o = i >> 8, c = i & 255;
        sw[o][c] = (o < 3) ? cls_w[o * 256 + c] : bbox_w[(o - 3) * 256 + c];
    }
    __syncthreads();

    int p = blockIdx.x * 128 + tid;
    if (p >= NPIX) return;

    const float4* row = (const float4*)(d_tt + (size_t)p * COUT);

    float acc[15];
#pragma unroll
    for (int o = 0; o < 15; o++) acc[o] = 0.f;

#pragma unroll 8
    for (int cc = 0; cc < 64; cc++) {
        float4 v = row[cc];
#pragma unroll
        for (int o = 0; o < 15; o++) {
            float4 w4 = *(const float4*)&sw[o][cc * 4];
            acc[o] = fmaf(w4.x, v.x, acc[o]);
            acc[o] = fmaf(w4.y, v.y, acc[o]);
            acc[o] = fmaf(w4.z, v.z, acc[o]);
            acc[o] = fmaf(w4.w, v.w, acc[o]);
        }
    }

#pragma unroll
    for (int a = 0; a < 3; a++) {
        float sc = acc[a] + cls_b[a];
        d_scores[p * 3 + a] = sc;
        unsigned kb = __float_as_uint(sc);
        kb = (kb & 0x80000000u) ? ~kb : (kb | 0x80000000u);
        atomicAdd(&d_hist[kb >> 18], 1);
#pragma unroll
        for (int j = 0; j < 4; j++)
            d_deltas[(p * 3 + a) * 4 + j] = acc[3 + a * 4 + j] + bbox_b[a * 4 + j];
    }
}

// ---------------- top-k: find cutoff histogram bin (vectorized) ----------------
__global__ void scan_kernel() {
    __shared__ int psum[256];
    int tid = threadIdx.x;
    const int4* h4 = (const int4*)&d_hist[tid * 64];
    int s = 0;
#pragma unroll
    for (int i = 0; i < 16; i++) {
        int4 v = h4[i];
        s += v.x + v.y + v.z + v.w;
    }
    psum[tid] = s;
    __syncthreads();
    if (tid == 0) {
        int acc = 0;
        int b = 0;
        for (b = 255; b >= 0; b--) {
            if (acc + psum[b] >= TOPK) break;
            acc += psum[b];
        }
        int bin = b * 64;
        for (int i = 63; i >= 0; i--) {
            int c = d_hist[b * 64 + i];
            if (acc + c >= TOPK) { bin = b * 64 + i; break; }
            acc += c;
        }
        d_cutbin = bin;
    }
}

// ---------------- collect candidates with bin >= cutoff ----------------
__global__ void collect_kernel() {
    int i = blockIdx.x * 256 + threadIdx.x;
    if (i >= NANCH) return;
    float v = d_scores[i];
    unsigned kb = __float_as_uint(v);
    kb = (kb & 0x80000000u) ? ~kb : (kb | 0x80000000u);
    if ((int)(kb >> 18) >= d_cutbin) {
        int pos = atomicAdd(&d_cand_cnt, 1);
        if (pos < MAXCAND) { d_cand_val[pos] = v; d_cand_idx[pos] = i; }
    }
}

// ---------------- bitonic sort candidates (desc by value, asc by idx) ----------------
__global__ void __launch_bounds__(1024) sort_kernel() {
    __shared__ float sv[MAXCAND];
    __shared__ int   si[MAXCAND];
    int tid = threadIdx.x;
    int n = d_cand_cnt;
    if (n > MAXCAND) n = MAXCAND;
    for (int i = tid; i < MAXCAND; i += 1024) {
        if (i < n) { sv[i] = d_cand_val[i]; si[i] = d_cand_idx[i]; }
        else       { sv[i] = -INFINITY;     si[i] = 0x7fffffff;   }
    }
    __syncthreads();
    for (int size = 2; size <= MAXCAND; size <<= 1) {
        for (int stride = size >> 1; stride > 0; stride >>= 1) {
            for (int t = tid; t < MAXCAND / 2; t += 1024) {
                int i = 2 * t - (t & (stride - 1));
                int j = i + stride;
                bool desc = ((i & size) == 0);
                float av = sv[i], bv = sv[j];
                int ai = si[i], bi = si[j];
                bool a_first = (av > bv) || (av == bv && ai < bi);
                if (desc != a_first) { sv[i] = bv; sv[j] = av; si[i] = bi; si[j] = ai; }
            }
            __syncthreads();
        }
    }
    for (int i = tid; i < TOPK; i += 1024) {
        d_top_score[i] = sv[i];
        d_top_idx[i] = si[i];
    }
}

// ---------------- decode + clip + valid ----------------
__global__ void __launch_bounds__(1024) decode_kernel(const int* pih, const int* piw) {
    int i = threadIdx.x;
    int vbit = 0;
    if (i < TOPK) {
        int idx = d_top_idx[i];
        int p = idx / 3;
        int a = idx - 3 * p;
        int y = p / 200;
        int x = p - 200 * y;
        int ih = pih[0], iw = piw[0];
        float sh = (float)(ih / FHH), swd = (float)(iw / FWW);
        float a1 = x * swd + c_ax1[a];
        float b1 = y * sh  + c_ay1[a];
        float a2 = x * swd + c_ax2[a];
        float b2 = y * sh  + c_ay2[a];
        float w = a2 - a1, h = b2 - b1;
        float cx = a1 + 0.5f * w, cy = b1 + 0.5f * h;
        float dx = d_deltas[idx * 4 + 0];
        float dy = d_deltas[idx * 4 + 1];
        float dw = fminf(d_deltas[idx * 4 + 2], XCLIP);
        float dh = fminf(d_deltas[idx * 4 + 3], XCLIP);
        float pcx = dx * w + cx, pcy = dy * h + cy;
        // correctly-rounded float exp via double (matches libm expf on host)
        float pw = (float)exp((double)dw) * w, ph = (float)exp((double)dh) * h;
        float x1 = pcx - 0.5f * pw, y1 = pcy - 0.5f * ph;
        float x2 = pcx + 0.5f * pw, y2 = pcy + 0.5f * ph;
        float fw_ = (float)iw, fh_ = (float)ih;
        x1 = fminf(fmaxf(x1, 0.f), fw_);
        y1 = fminf(fmaxf(y1, 0.f), fh_);
        x2 = fminf(fmaxf(x2, 0.f), fw_);
        y2 = fminf(fmaxf(y2, 0.f), fh_);
        d_boxes[i * 4 + 0] = x1;
        d_boxes[i * 4 + 1] = y1;
        d_boxes[i * 4 + 2] = x2;
        d_boxes[i * 4 + 3] = y2;
        vbit = (x2 - x1 >= 0.001f) && (y2 - y1 >= 0.001f);
    }
    unsigned bal = __ballot_sync(0xffffffffu, vbit);
    if ((threadIdx.x & 31) == 0) d_validw[threadIdx.x >> 5] = bal;
}

// ---------------- IoU suppression bitmask ----------------
__global__ void mask_kernel() {
    int i = blockIdx.x;
    int w = threadIdx.x;
    float ix1 = d_boxes[i * 4 + 0], iy1 = d_boxes[i * 4 + 1];
    float ix2 = d_boxes[i * 4 + 2], iy2 = d_boxes[i * 4 + 3];
    float ia = (ix2 - ix1) * (iy2 - iy1);
    unsigned m = 0;
    int jbase = w * 32;
    for (int b = 0; b < 32; b++) {
        int j = jbase + b;
        if (j > i && j < TOPK) {
            float jx1 = d_boxes[j * 4 + 0], jy1 = d_boxes[j * 4 + 1];
            float jx2 = d_boxes[j * 4 + 2], jy2 = d_boxes[j * 4 + 3];
            float ja = (jx2 - jx1) * (jy2 - jy1);
            float xl = fmaxf(ix1, jx1), yt = fmaxf(iy1, jy1);
            float xr = fminf(ix2, jx2), yb = fminf(iy2, jy2);
            float inter = fmaxf(xr - xl, 0.f) * fmaxf(yb - yt, 0.f);
            float uni = ia + ja - inter;
            float iou = inter / (uni + 1e-8f);
            if (iou > 0.7f) m |= 1u << b;
        }
    }
    d_mask[i * 32 + w] = m;
}

// ---------------- serial greedy NMS (warp 0) + output write ----------------
__global__ void __launch_bounds__(1024) nms_out_kernel(float* out, int out_size) {
    __shared__ unsigned skeep[32];
    int tid = threadIdx.x;
    if (tid < 32) {
        unsigned myk = d_validw[tid];
        unsigned nextm = d_mask[tid];   // row 0
        for (int i = 0; i < TOPK; i++) {
            unsigned m = nextm;
            if (i + 1 < TOPK) nextm = d_mask[(i + 1) * 32 + tid];
            unsigned wv = __shfl_sync(0xffffffffu, myk, i >> 5);
            if ((wv >> (i & 31)) & 1u) myk &= ~m;
        }
        skeep[tid] = myk;
    }
    __syncthreads();
    for (int i = tid; i < TOPK; i += 1024) {
        bool k = (skeep[i >> 5] >> (i & 31)) & 1u;
        float x1 = 0.f, y1 = 0.f, x2 = 0.f, y2 = 0.f, sc = 0.f;
        if (k) {
            x1 = d_boxes[i * 4 + 0];
            y1 = d_boxes[i * 4 + 1];
            x2 = d_boxes[i * 4 + 2];
            y2 = d_boxes[i * 4 + 3];
            sc = d_top_score[i];
        }
        out[i * 5 + 0] = x1;
        out[i * 5 + 1] = y1;
        out[i * 5 + 2] = x2;
        out[i * 5 + 3] = y2;
        out[i * 5 + 4] = sc;
        if (out_size >= TOPK * 6) out[TOPK * 5 + i] = k ? 1.f : 0.f;
    }
}

// ---------------- launch ----------------
extern "C" void kernel_launch(void* const* d_in, const int* in_sizes, int n_in,
                              void* d_out, int out_size) {
    const float* feat   = (const float*)d_in[0];
    const float* conv_w = (const float*)d_in[1];
    const float* conv_b = (const float*)d_in[2];
    const float* cls_w  = (const float*)d_in[3];
    const float* cls_b  = (const float*)d_in[4];
    const float* bbox_w = (const float*)d_in[5];
    const float* bbox_b = (const float*)d_in[6];
    const int*   ih     = (const int*)d_in[7];
    const int*   iw     = (const int*)d_in[8];
    (void)in_sizes; (void)n_in;

    dim3 tgrid(KD / 32, COUT / 32);
    dim3 tblk(32, 8);
    wtrans_kernel<<<tgrid, tblk>>>(conv_w);
    dim3 cgrid((NPIX + 127) / 128, COUT / 128);
    conv3x3_relu<<<cgrid, 256>>>(feat, conv_b);
    head_kernel<<<(NPIX + 127) / 128, 128>>>(cls_w, cls_b, bbox_w, bbox_b);
    scan_kernel<<<1, 256>>>();
    collect_kernel<<<(NANCH + 255) / 256, 256>>>();
    sort_kernel<<<1, 1024>>>();
    decode_kernel<<<1, 1024>>>(ih, iw);
    mask_kernel<<<TOPK, 32>>>();
    nms_out_kernel<<<1, 1024>>>((float*)d_out, out_size);
}